// round 6
// baseline (speedup 1.0000x reference)
#include <cuda_runtime.h>
#include <math.h>
#include <stdint.h>

typedef unsigned long long ull;

#define KA 12
#define HSZ 4608
#define INP 5024
#define EPSB 1e-5f
#define NPX 6912.f

// big gemm tiling
#define CSZ 628
#define CPAD 640
#define LSTR 642
#define NCH 8
#define NRB 108
// head gemm tiling
#define CSZ2 768
#define LSTR2 770
#define NCH2 6
#define HROWS 320

// scratch
__device__ __align__(16) float g_h1[KA*16*576];
__device__ __align__(16) float g_h2[KA*16*576];
__device__ __align__(16) float g_h3[KA*8*576];
__device__ float g_p1[36*16*2];
__device__ float g_p2[36*16*2];
__device__ float g_p3[36*8*2];
__device__ float g_op[192], g_om[192], g_mm[192];
__device__ __align__(16) float g_lsp[6*INP*2];
__device__ __align__(16) float g_part[(size_t)NCH*13824*KA];
__device__ __align__(16) float g_hp[6*HSZ*2];
__device__ __align__(16) float g_part2[(size_t)NCH2*HROWS*KA];

// grid barrier state (sense-reversal; net-zero count per use, sense just toggles)
__device__ volatile unsigned g_bar_sense = 0u;
__device__ unsigned g_bar_cnt = 0u;

__device__ __forceinline__ void gridbar(unsigned nb){
    __threadfence();
    __syncthreads();
    if (threadIdx.x == 0){
        unsigned s = g_bar_sense;
        if (atomicAdd(&g_bar_cnt, 1u) == nb - 1u){
            g_bar_cnt = 0u;
            __threadfence();
            g_bar_sense = s ^ 1u;
        } else {
            while (g_bar_sense == s) { }
        }
        __threadfence();
    }
    __syncthreads();
}

__device__ __forceinline__ ull dup2(float a){ ull r; asm("mov.b64 %0,{%1,%1};":"=l"(r):"f"(a)); return r; }
__device__ __forceinline__ ull fma2(ull a, ull b, ull c){ ull d; asm("fma.rn.f32x2 %0,%1,%2,%3;":"=l"(d):"l"(a),"l"(b),"l"(c)); return d; }
__device__ __forceinline__ ull add2(ull a, ull b){ ull d; asm("add.rn.f32x2 %0,%1,%2;":"=l"(d):"l"(a),"l"(b)); return d; }

__global__ void k_nop(){}

// ================= fused pre-GEMM pipeline: 36 blocks x 192 threads =================
__global__ __launch_bounds__(192) void k_pre(
    const float* __restrict__ x,  const float* __restrict__ w1,
    const float* __restrict__ w2, const float* __restrict__ g1, const float* __restrict__ bb1,
    const float* __restrict__ w3, const float* __restrict__ g2, const float* __restrict__ bb2,
    const float* __restrict__ g3, const float* __restrict__ bb3,
    const float* __restrict__ p,  const float* __restrict__ m,
    const float* __restrict__ phys_w, const float* __restrict__ phys_b,
    const float* __restrict__ ment_w, const float* __restrict__ ment_b,
    const float* __restrict__ vis)
{
    __shared__ __align__(16) float sm[8000];
    const int blk = blockIdx.x, tid = threadIdx.x;
    const int warp = tid >> 5, lane = tid & 31;

    // ---------- P1: conv1 (1x1 over c,d; bias cancels in BN) + stats ----------
    {
        float* ws = sm;                                   // 4096
        float (*sred)[16][2] = (float(*)[16][2])(sm + 4096);
        int b = blk / 3, strip = blk % 3;
        for (int i = tid; i < 4096; i += 192) ws[i] = w1[i];
        __syncthreads();
        int px = strip*192 + tid;
        float acc[16];
#pragma unroll
        for (int o = 0; o < 16; o++) acc[o] = 0.f;
        const float* xb = x + (size_t)b*147456 + px;
#pragma unroll 16
        for (int cd = 0; cd < 256; cd++){
            float xv = xb[(size_t)cd*576];
#pragma unroll
            for (int o = 0; o < 16; o++) acc[o] += xv * ws[o*256+cd];
        }
#pragma unroll
        for (int o = 0; o < 16; o++) g_h1[((size_t)b*16+o)*576 + px] = acc[o];
#pragma unroll
        for (int o = 0; o < 16; o++){
            float s = acc[o], q = acc[o]*acc[o];
#pragma unroll
            for (int off = 16; off; off >>= 1){
                s += __shfl_xor_sync(0xffffffffu, s, off);
                q += __shfl_xor_sync(0xffffffffu, q, off);
            }
            if (lane == 0){ sred[warp][o][0] = s; sred[warp][o][1] = q; }
        }
        __syncthreads();
        if (tid < 16){
            float S = 0.f, Q = 0.f;
#pragma unroll
            for (int w = 0; w < 6; w++){ S += sred[w][tid][0]; Q += sred[w][tid][1]; }
            g_p1[blk*32 + tid*2+0] = S;
            g_p1[blk*32 + tid*2+1] = Q;
        }
        // tiny agent linears on block 0 (independent of convs)
        if (blk == 0 && tid < 192){
            int j = tid/16, t = tid%16;
            float s1 = phys_b[t], s2 = ment_b[t], s3 = ment_b[t];
            for (int k = 0; k < 16; k++){
                s1 += p[j*16+k] * phys_w[t*16+k];
                float mv = m[j*16+k];
                s2 += mv * ment_w[t*16+k];
                s3 += 0.9f * mv * ment_w[t*16+k];
            }
            g_op[tid] = fmaxf(s1, 0.f);
            g_om[tid] = fmaxf(s2, 0.f);
            g_mm[tid] = fmaxf(s3, 0.f);
        }
    }
    gridbar(36);

    // ---------- P2: bn1 + relu -> conv2 3x3 SAME + stats ----------
    {
        float (*in_s)[10][24] = (float(*)[10][24])sm;     // 3840
        float* ws = sm + 3840;                            // 2304
        float* sc = sm + 6144;
        float* sh = sm + 6160;
        float (*sred)[16][2] = (float(*)[16][2])(sm + 6176);
        int b = blk / 3, ty = blk % 3;
        if (tid < 16){
            float S = 0.f, Q = 0.f;
#pragma unroll
            for (int i = 0; i < 36; i++){ S += g_p1[i*32+tid*2]; Q += g_p1[i*32+tid*2+1]; }
            float mu = S/NPX, var = Q/NPX - mu*mu;
            float r = rsqrtf(var + EPSB) * g1[tid];
            sc[tid] = r; sh[tid] = bb1[tid] - mu*r;
        }
        for (int i = tid; i < 2304; i += 192) ws[i] = w2[i];
        __syncthreads();
        int r0 = 8*ty - 1;
        for (int i = tid; i < 3840; i += 192){
            int ci = i/240, rr = (i/24)%10, cc = i%24;
            int gy = r0 + rr; float v = 0.f;
            if (gy >= 0 && gy < 24)
                v = fmaxf(g_h1[((size_t)b*16+ci)*576 + gy*24 + cc]*sc[ci] + sh[ci], 0.f);
            in_s[ci][rr][cc] = v;
        }
        __syncthreads();
        int ly = tid/24, lx = tid%24, gy = 8*ty + ly;
        float acc[16];
#pragma unroll
        for (int o = 0; o < 16; o++) acc[o] = 0.f;
        for (int ci = 0; ci < 16; ci++){
#pragma unroll
            for (int ky = 0; ky < 3; ky++){
#pragma unroll
                for (int kx = 0; kx < 3; kx++){
                    int gx = lx + kx - 1;
                    if (gx >= 0 && gx < 24){
                        float xv = in_s[ci][ly+ky][gx];
#pragma unroll
                        for (int o = 0; o < 16; o++) acc[o] += xv * ws[(o*16+ci)*9 + ky*3 + kx];
                    }
                }
            }
        }
#pragma unroll
        for (int o = 0; o < 16; o++) g_h2[((size_t)b*16+o)*576 + gy*24 + lx] = acc[o];
#pragma unroll
        for (int o = 0; o < 16; o++){
            float s = acc[o], q = acc[o]*acc[o];
#pragma unroll
            for (int off = 16; off; off >>= 1){
                s += __shfl_xor_sync(0xffffffffu, s, off);
                q += __shfl_xor_sync(0xffffffffu, q, off);
            }
            if (lane == 0){ sred[warp][o][0] = s; sred[warp][o][1] = q; }
        }
        __syncthreads();
        if (tid < 16){
            float S = 0.f, Q = 0.f;
#pragma unroll
            for (int w = 0; w < 6; w++){ S += sred[w][tid][0]; Q += sred[w][tid][1]; }
            g_p2[blk*32 + tid*2+0] = S;
            g_p2[blk*32 + tid*2+1] = Q;
        }
    }
    gridbar(36);

    // ---------- P3: bn2 + relu -> conv3 5x5 SAME + stats ----------
    {
        float (*in_s)[12][24] = (float(*)[12][24])sm;     // 4608
        float* ws = sm + 4608;                            // 3200
        float* sc = sm + 7808;
        float* sh = sm + 7824;
        float (*sred)[8][2] = (float(*)[8][2])(sm + 7840);
        int b = blk / 3, ty = blk % 3;
        if (tid < 16){
            float S = 0.f, Q = 0.f;
#pragma unroll
            for (int i = 0; i < 36; i++){ S += g_p2[i*32+tid*2]; Q += g_p2[i*32+tid*2+1]; }
            float mu = S/NPX, var = Q/NPX - mu*mu;
            float r = rsqrtf(var + EPSB) * g2[tid];
            sc[tid] = r; sh[tid] = bb2[tid] - mu*r;
        }
        for (int i = tid; i < 3200; i += 192) ws[i] = w3[i];
        __syncthreads();
        int r0 = 8*ty - 2;
        for (int i = tid; i < 4608; i += 192){
            int ci = i/288, rr = (i/24)%12, cc = i%24;
            int gy = r0 + rr; float v = 0.f;
            if (gy >= 0 && gy < 24)
                v = fmaxf(g_h2[((size_t)b*16+ci)*576 + gy*24 + cc]*sc[ci] + sh[ci], 0.f);
            in_s[ci][rr][cc] = v;
        }
        __syncthreads();
        int ly = tid/24, lx = tid%24, gy = 8*ty + ly;
        float acc[8];
#pragma unroll
        for (int o = 0; o < 8; o++) acc[o] = 0.f;
        for (int ci = 0; ci < 16; ci++){
#pragma unroll
            for (int ky = 0; ky < 5; ky++){
#pragma unroll
                for (int kx = 0; kx < 5; kx++){
                    int gx = lx + kx - 2;
                    if (gx >= 0 && gx < 24){
                        float xv = in_s[ci][ly+ky][gx];
#pragma unroll
                        for (int o = 0; o < 8; o++) acc[o] += xv * ws[(o*16+ci)*25 + ky*5 + kx];
                    }
                }
            }
        }
#pragma unroll
        for (int o = 0; o < 8; o++) g_h3[((size_t)b*8+o)*576 + gy*24 + lx] = acc[o];
#pragma unroll
        for (int o = 0; o < 8; o++){
            float s = acc[o], q = acc[o]*acc[o];
#pragma unroll
            for (int off = 16; off; off >>= 1){
                s += __shfl_xor_sync(0xffffffffu, s, off);
                q += __shfl_xor_sync(0xffffffffu, q, off);
            }
            if (lane == 0){ sred[warp][o][0] = s; sred[warp][o][1] = q; }
        }
        __syncthreads();
        if (tid < 8){
            float S = 0.f, Q = 0.f;
#pragma unroll
            for (int w = 0; w < 6; w++){ S += sred[w][tid][0]; Q += sred[w][tid][1]; }
            g_p3[blk*16 + tid*2+0] = S;
            g_p3[blk*16 + tid*2+1] = Q;
        }
    }
    gridbar(36);

    // ---------- P4: bn3 scale + assemble lstm_in into agent-pair planes ----------
    {
        float* sc = sm;
        float* sh = sm + 8;
        if (tid < 8){
            float S = 0.f, Q = 0.f;
#pragma unroll
            for (int i = 0; i < 36; i++){ S += g_p3[i*16+tid*2]; Q += g_p3[i*16+tid*2+1]; }
            float mu = S/NPX, var = Q/NPX - mu*mu;
            float r = rsqrtf(var + EPSB) * g3[tid];
            sc[tid] = r; sh[tid] = bb3[tid] - mu*r;
        }
        __syncthreads();
        for (int idx = blk*192 + tid; idx < KA*INP; idx += 36*192){
            int b = idx / INP, col = idx % INP;
            float v;
            if (col < 4608){
                int ch = col/576, px = col%576;
                v = fmaxf(g_h3[((size_t)b*8+ch)*576 + px]*sc[ch] + sh[ch], 0.f);
            } else if (col < 4624) v = g_op[b*16 + col - 4608];
            else if (col < 4640)   v = g_om[b*16 + col - 4624];
            else if (col < 4832){ int r = col - 4640; v = vis[b*12 + r/16] * g_op[r]; }
            else                  v = g_mm[col - 4832];
            g_lsp[((size_t)(b>>1)*INP + col)*2 + (b&1)] = v;
        }
    }
}

// ================= big weight-streaming GEMM (i,g,o rows; f gate dead) =================
__global__ __launch_bounds__(128, 5) void k_gemm(const float* __restrict__ w_ih){
    __shared__ __align__(16) ull ls[6*LSTR];
    const int rblk = blockIdx.x, chunk = blockIdx.y, tid = threadIdx.x;
    const int c0 = chunk * CSZ;
    const ull* gsrc = (const ull*)g_lsp;
    for (int i = tid; i < 6*CPAD; i += 128){
        int pp = i/CPAD, c = i - pp*CPAD;
        ls[pp*LSTR + c] = (c < CSZ) ? gsrc[(size_t)pp*INP + c0 + c] : 0ULL;
    }
    __syncthreads();
    const int warp = tid>>5, lane = tid&31;
    const int cb = 4*lane;
    for (int pass = 0; pass < 8; pass++){
        int ridx = rblk*128 + pass*16 + warp*4;
        int gate = ridx / 4608;
        int gm = (gate==0) ? 0 : (gate==1 ? 2 : 3);
        const float* __restrict__ wr = w_ih + (size_t)(gm*4608 + ridx - gate*4608)*INP + c0;
        ull acc[4][6];
#pragma unroll
        for (int r = 0; r < 4; r++)
#pragma unroll
            for (int pp = 0; pp < 6; pp++) acc[r][pp] = 0ULL;
#pragma unroll
        for (int ii = 0; ii < 5; ii++){
            int c = ii*128 + cb;
            float4 w0, w1, w2, w3;
            if (c < CSZ){
                w0 = *(const float4*)(wr + c);
                w1 = *(const float4*)(wr + INP + c);
                w2 = *(const float4*)(wr + 2*INP + c);
                w3 = *(const float4*)(wr + 3*INP + c);
            } else {
                w0 = make_float4(0.f,0.f,0.f,0.f); w1 = w0; w2 = w0; w3 = w0;
            }
            const ull* lp = ls + c;
#pragma unroll
            for (int j = 0; j < 4; j++){
                ull W0 = dup2(j==0?w0.x:j==1?w0.y:j==2?w0.z:w0.w);
                ull W1 = dup2(j==0?w1.x:j==1?w1.y:j==2?w1.z:w1.w);
                ull W2 = dup2(j==0?w2.x:j==1?w2.y:j==2?w2.z:w2.w);
                ull W3 = dup2(j==0?w3.x:j==1?w3.y:j==2?w3.z:w3.w);
#pragma unroll
                for (int pp = 0; pp < 6; pp++){
                    ull l = lp[pp*LSTR + j];
                    acc[0][pp] = fma2(W0, l, acc[0][pp]);
                    acc[1][pp] = fma2(W1, l, acc[1][pp]);
                    acc[2][pp] = fma2(W2, l, acc[2][pp]);
                    acc[3][pp] = fma2(W3, l, acc[3][pp]);
                }
            }
        }
#pragma unroll
        for (int r = 0; r < 4; r++)
#pragma unroll
            for (int pp = 0; pp < 6; pp++){
                ull v = acc[r][pp];
#pragma unroll
                for (int off = 16; off; off >>= 1)
                    v = add2(v, __shfl_xor_sync(0xffffffffu, v, off));
                acc[r][pp] = v;
            }
        if (lane < 12){
            int pp = lane>>1, hi = lane&1;
#pragma unroll
            for (int r = 0; r < 4; r++){
                float lo_, hi_;
                asm("mov.b64 {%0,%1}, %2;" : "=f"(lo_), "=f"(hi_) : "l"(acc[r][pp]));
                g_part[((size_t)chunk*13824 + ridx + r)*KA + lane] = hi ? hi_ : lo_;
            }
        }
    }
}

// ================= fused post-GEMM: fin + head GEMM + heads: 120 blocks x 128 =================
__global__ __launch_bounds__(128) void k_post(
    const float* __restrict__ b_ih, const float* __restrict__ b_hh,
    const float* __restrict__ ah_w, const float* __restrict__ inf_w,
    const float* __restrict__ ah_b, const float* __restrict__ inf_b,
    const float* __restrict__ act_w, const float* __restrict__ act_b,
    float* __restrict__ out)
{
    __shared__ __align__(16) ull lsu[6*LSTR2];
    const int blk = blockIdx.x, tid = threadIdx.x;

    // ---------- P1: sum gemm partials + LSTM activations -> relu(h) planes ----------
    for (int idx = blk*128 + tid; idx < KA*HSZ; idx += 120*128){
        int b = idx % KA, h = idx / KA;
        float si = b_ih[h] + b_hh[h];
        float sg = b_ih[9216 + h] + b_hh[9216 + h];
        float so = b_ih[13824 + h] + b_hh[13824 + h];
#pragma unroll
        for (int ch = 0; ch < NCH; ch++){
            const float* pp = g_part + (size_t)ch*13824*KA;
            si += pp[(size_t)h*KA + b];
            sg += pp[(size_t)(4608 + h)*KA + b];
            so += pp[(size_t)(9216 + h)*KA + b];
        }
        float c  = (1.f/(1.f + __expf(-si))) * tanhf(sg);
        float hv = (1.f/(1.f + __expf(-so))) * tanhf(c);
        g_hp[((size_t)(b>>1)*HSZ + h)*2 + (b&1)] = fmaxf(hv, 0.f);
    }
    gridbar(120);

    // ---------- P2: head GEMM (ah rows 0..127, inf rows 128..319) ----------
    {
        int rblk = blk % 20, chunk = blk / 20;
        int c0 = chunk * CSZ2;
        const ull* gsrc = (const ull*)g_hp;
        for (int i = tid; i < 6*CSZ2; i += 128){
            int pp = i/CSZ2, c = i - pp*CSZ2;
            lsu[pp*LSTR2 + c] = gsrc[(size_t)pp*HSZ + c0 + c];
        }
        __syncthreads();
        int warp = tid>>5, lane = tid&31;
        int cb = 2*lane;
        int ridx = rblk*16 + warp*4;
        const float* __restrict__ wb = (ridx < 128) ? ah_w + (size_t)ridx*HSZ + c0
                                                    : inf_w + (size_t)(ridx-128)*HSZ + c0;
        ull acc[4][6];
#pragma unroll
        for (int r = 0; r < 4; r++)
#pragma unroll
            for (int pp = 0; pp < 6; pp++) acc[r][pp] = 0ULL;
#pragma unroll
        for (int i = 0; i < 12; i++){
            int c = i*64 + cb;
            float2 wv0 = *(const float2*)(wb + c);
            float2 wv1 = *(const float2*)(wb + HSZ + c);
            float2 wv2 = *(const float2*)(wb + 2*HSZ + c);
            float2 wv3 = *(const float2*)(wb + 3*HSZ + c);
#pragma unroll
            for (int pp = 0; pp < 6; pp++){
                ulonglong2 lv = *(const ulonglong2*)&lsu[pp*LSTR2 + c];
                acc[0][pp] = fma2(dup2(wv0.x), lv.x, acc[0][pp]);
                acc[0][pp] = fma2(dup2(wv0.y), lv.y, acc[0][pp]);
                acc[1][pp] = fma2(dup2(wv1.x), lv.x, acc[1][pp]);
                acc[1][pp] = fma2(dup2(wv1.y), lv.y, acc[1][pp]);
                acc[2][pp] = fma2(dup2(wv2.x), lv.x, acc[2][pp]);
                acc[2][pp] = fma2(dup2(wv2.y), lv.y, acc[2][pp]);
                acc[3][pp] = fma2(dup2(wv3.x), lv.x, acc[3][pp]);
                acc[3][pp] = fma2(dup2(wv3.y), lv.y, acc[3][pp]);
            }
        }
#pragma unroll
        for (int r = 0; r < 4; r++)
#pragma unroll
            for (int pp = 0; pp < 6; pp++){
                ull v = acc[r][pp];
#pragma unroll
                for (int off = 16; off; off >>= 1)
                    v = add2(v, __shfl_xor_sync(0xffffffffu, v, off));
                acc[r][pp] = v;
            }
        if ((tid&31) < 12){
            int lane2 = tid&31;
            int pp = lane2>>1, hi = lane2&1;
#pragma unroll
            for (int r = 0; r < 4; r++){
                float lo_, hi_;
                asm("mov.b64 {%0,%1}, %2;" : "=f"(lo_), "=f"(hi_) : "l"(acc[r][pp]));
                g_part2[((size_t)chunk*HROWS + ridx + r)*KA + lane2] = hi ? hi_ : lo_;
            }
        }
    }
    gridbar(120);

    // ---------- P3: head finalize + action head (block 0 only) ----------
    if (blk == 0){
        float* t = (float*)lsu;   // 12*128 floats, reuse smem
        for (int idx = tid; idx < HROWS*KA; idx += 128){
            int b = idx % KA, r = idx / KA;
            float s = (r < 128) ? ah_b[r] : inf_b[r-128];
#pragma unroll
            for (int ch = 0; ch < NCH2; ch++)
                s += g_part2[((size_t)ch*HROWS + r)*KA + b];
            if (r < 128) t[b*128 + r] = fmaxf(s, 0.f);
            else         out[192 + b*192 + (r-128)] = s;
        }
        __syncthreads();
        for (int i = tid; i < 192; i += 128){
            int b = i/16, a = i%16;
            float s = act_b[a];
            for (int q = 0; q < 128; q++) s += t[b*128+q] * act_w[a*128+q];
            out[b*16 + a] = s;
        }
    }
}

extern "C" void kernel_launch(void* const* d_in, const int* in_sizes, int n_in,
                              void* d_out, int out_size){
    const float* x       = (const float*)d_in[0];
    const float* p       = (const float*)d_in[1];
    const float* m       = (const float*)d_in[2];
    const float* vis     = (const float*)d_in[3];
    const float* conv1_w = (const float*)d_in[4];
    const float* bn1_g   = (const float*)d_in[6];
    const float* bn1_b   = (const float*)d_in[7];
    const float* conv2_w = (const float*)d_in[8];
    const float* bn2_g   = (const float*)d_in[10];
    const float* bn2_b   = (const float*)d_in[11];
    const float* conv3_w = (const float*)d_in[12];
    const float* bn3_g   = (const float*)d_in[14];
    const float* bn3_b   = (const float*)d_in[15];
    const float* phys_w  = (const float*)d_in[16];
    const float* phys_b  = (const float*)d_in[17];
    const float* ment_w  = (const float*)d_in[18];
    const float* ment_b  = (const float*)d_in[19];
    const float* w_ih    = (const float*)d_in[20];
    const float* b_ih    = (const float*)d_in[22];
    const float* b_hh    = (const float*)d_in[23];
    const float* ah_w    = (const float*)d_in[24];
    const float* ah_b    = (const float*)d_in[25];
    const float* act_w   = (const float*)d_in[26];
    const float* act_b   = (const float*)d_in[27];
    const float* inf_w   = (const float*)d_in[28];
    const float* inf_b   = (const float*)d_in[29];
    float* out = (float*)d_out;

    k_nop<<<1, 32>>>();                                        // 0 (ncu offset pad)
    k_pre<<<36, 192>>>(x, conv1_w,
                       conv2_w, bn1_g, bn1_b,
                       conv3_w, bn2_g, bn2_b,
                       bn3_g, bn3_b,
                       p, m, phys_w, phys_b, ment_w, ment_b,
                       vis);                                   // 1
    k_nop<<<1, 32>>>();                                        // 2 (ncu offset pad)
    k_gemm<<<dim3(NRB, NCH), 128>>>(w_ih);                     // 3  <- ncu -s 5 (offset 2)
    k_post<<<120, 128>>>(b_ih, b_hh, ah_w, inf_w,
                         ah_b, inf_b, act_w, act_b, out);      // 4
}

// round 7
// speedup vs baseline: 1.7900x; 1.7900x over previous
#include <cuda_runtime.h>
#include <math.h>
#include <stdint.h>

typedef unsigned long long ull;

#define KA 12
#define HSZ 4608
#define INP 5024
#define EPSB 1e-5f
#define NPX 6912.f

// big gemm tiling: 8 chunks x 628 cols (8*628 = 5024 exactly), 54 row-blocks x 256 rows
#define CSZ 628
#define CPAD 640
#define LSTR 640
#define NCH 8
#define NRB 54
// head gemm tiling
#define CSZ2 768
#define LSTR2 770
#define NCH2 6
#define HROWS 320

// scratch
__device__ __align__(16) float g_h1[KA*16*576];
__device__ __align__(16) float g_h2[KA*16*576];
__device__ __align__(16) float g_h3[KA*8*576];
__device__ float g_p1[36*16*2];
__device__ float g_p2[36*16*2];
__device__ float g_p3[36*8*2];
__device__ float g_op[192], g_om[192], g_mm[192];
__device__ __align__(16) float g_part[(size_t)NCH*13824*KA];
__device__ __align__(16) float g_hp[6*HSZ*2];
__device__ __align__(16) float g_part2[(size_t)NCH2*HROWS*KA];

__device__ __forceinline__ ull pk2(float a, float b){ ull r; asm("mov.b64 %0,{%1,%2};":"=l"(r):"f"(a),"f"(b)); return r; }
__device__ __forceinline__ ull dup2(float a){ ull r; asm("mov.b64 %0,{%1,%1};":"=l"(r):"f"(a)); return r; }
__device__ __forceinline__ ull fma2(ull a, ull b, ull c){ ull d; asm("fma.rn.f32x2 %0,%1,%2,%3;":"=l"(d):"l"(a),"l"(b),"l"(c)); return d; }
__device__ __forceinline__ ull add2(ull a, ull b){ ull d; asm("add.rn.f32x2 %0,%1,%2;":"=l"(d):"l"(a),"l"(b)); return d; }

// ---------- conv1: 1x1 over (c,d) (bias cancels in BN) + stats; block(0,0) also does agent linears ----------
__global__ __launch_bounds__(192) void k_conv1(const float* __restrict__ x,
                                               const float* __restrict__ w1,
                                               const float* __restrict__ p,  const float* __restrict__ m,
                                               const float* __restrict__ phys_w, const float* __restrict__ phys_b,
                                               const float* __restrict__ ment_w, const float* __restrict__ ment_b){
    __shared__ float ws[4096];
    __shared__ float sred[6][16][2];
    int b = blockIdx.x, strip = blockIdx.y, tid = threadIdx.x;
    int warp = tid>>5, lane = tid&31;
    for (int i = tid; i < 4096; i += 192) ws[i] = w1[i];
    __syncthreads();
    int px = strip*192 + tid;
    float acc[16];
#pragma unroll
    for (int o = 0; o < 16; o++) acc[o] = 0.f;
    const float* xb = x + (size_t)b*147456 + px;
#pragma unroll 16
    for (int cd = 0; cd < 256; cd++){
        float xv = xb[(size_t)cd*576];
#pragma unroll
        for (int o = 0; o < 16; o++) acc[o] += xv * ws[o*256+cd];
    }
#pragma unroll
    for (int o = 0; o < 16; o++) g_h1[((size_t)b*16+o)*576 + px] = acc[o];
#pragma unroll
    for (int o = 0; o < 16; o++){
        float s = acc[o], q = acc[o]*acc[o];
#pragma unroll
        for (int off = 16; off; off >>= 1){
            s += __shfl_xor_sync(0xffffffffu, s, off);
            q += __shfl_xor_sync(0xffffffffu, q, off);
        }
        if (lane == 0){ sred[warp][o][0] = s; sred[warp][o][1] = q; }
    }
    __syncthreads();
    if (tid < 16){
        int blk = b*3 + strip;
        float S = 0.f, Q = 0.f;
#pragma unroll
        for (int w = 0; w < 6; w++){ S += sred[w][tid][0]; Q += sred[w][tid][1]; }
        g_p1[blk*32 + tid*2+0] = S;
        g_p1[blk*32 + tid*2+1] = Q;
    }
    if (b == 0 && strip == 0){
        int j = tid/16, t = tid%16;
        float s1 = phys_b[t], s2 = ment_b[t], s3 = ment_b[t];
        for (int k = 0; k < 16; k++){
            s1 += p[j*16+k] * phys_w[t*16+k];
            float mv = m[j*16+k];
            s2 += mv * ment_w[t*16+k];
            s3 += 0.9f * mv * ment_w[t*16+k];
        }
        g_op[tid] = fmaxf(s1, 0.f);
        g_om[tid] = fmaxf(s2, 0.f);
        g_mm[tid] = fmaxf(s3, 0.f);
    }
}

// ---------- conv2: bn1 from partials + relu -> 3x3 SAME + stats ----------
__global__ __launch_bounds__(192) void k_conv2(const float* __restrict__ w2,
                                               const float* __restrict__ g1,
                                               const float* __restrict__ bb1){
    __shared__ float in_s[16][10][24];
    __shared__ float ws[2304];
    __shared__ float sc[16], sh[16];
    __shared__ float sred[6][16][2];
    int b = blockIdx.x, ty = blockIdx.y, tid = threadIdx.x;
    int warp = tid>>5, lane = tid&31;
    if (tid < 16){
        float S = 0.f, Q = 0.f;
#pragma unroll
        for (int i = 0; i < 36; i++){ S += g_p1[i*32+tid*2]; Q += g_p1[i*32+tid*2+1]; }
        float mu = S/NPX, var = Q/NPX - mu*mu;
        float r = rsqrtf(var + EPSB) * g1[tid];
        sc[tid] = r; sh[tid] = bb1[tid] - mu*r;
    }
    for (int i = tid; i < 2304; i += 192) ws[i] = w2[i];
    __syncthreads();
    int r0 = 8*ty - 1;
    for (int i = tid; i < 3840; i += 192){
        int ci = i/240, rr = (i/24)%10, cc = i%24;
        int gy = r0 + rr; float v = 0.f;
        if (gy >= 0 && gy < 24)
            v = fmaxf(g_h1[((size_t)b*16+ci)*576 + gy*24 + cc]*sc[ci] + sh[ci], 0.f);
        in_s[ci][rr][cc] = v;
    }
    __syncthreads();
    int ly = tid/24, lx = tid%24, gy = 8*ty + ly;
    float acc[16];
#pragma unroll
    for (int o = 0; o < 16; o++) acc[o] = 0.f;
    for (int ci = 0; ci < 16; ci++){
#pragma unroll
        for (int ky = 0; ky < 3; ky++){
#pragma unroll
            for (int kx = 0; kx < 3; kx++){
                int gx = lx + kx - 1;
                if (gx >= 0 && gx < 24){
                    float xv = in_s[ci][ly+ky][gx];
#pragma unroll
                    for (int o = 0; o < 16; o++) acc[o] += xv * ws[(o*16+ci)*9 + ky*3 + kx];
                }
            }
        }
    }
#pragma unroll
    for (int o = 0; o < 16; o++) g_h2[((size_t)b*16+o)*576 + gy*24 + lx] = acc[o];
#pragma unroll
    for (int o = 0; o < 16; o++){
        float s = acc[o], q = acc[o]*acc[o];
#pragma unroll
        for (int off = 16; off; off >>= 1){
            s += __shfl_xor_sync(0xffffffffu, s, off);
            q += __shfl_xor_sync(0xffffffffu, q, off);
        }
        if (lane == 0){ sred[warp][o][0] = s; sred[warp][o][1] = q; }
    }
    __syncthreads();
    if (tid < 16){
        float S = 0.f, Q = 0.f;
#pragma unroll
        for (int w = 0; w < 6; w++){ S += sred[w][tid][0]; Q += sred[w][tid][1]; }
        int blk = b*3 + ty;
        g_p2[blk*32 + tid*2+0] = S;
        g_p2[blk*32 + tid*2+1] = Q;
    }
}

// ---------- conv3: bn2 from partials + relu -> 5x5 SAME + stats ----------
__global__ __launch_bounds__(192) void k_conv3(const float* __restrict__ w3,
                                               const float* __restrict__ g2,
                                               const float* __restrict__ bb2){
    __shared__ float in_s[16][12][24];
    __shared__ float ws[3200];
    __shared__ float sc[16], sh[16];
    __shared__ float sred[6][8][2];
    int b = blockIdx.x, ty = blockIdx.y, tid = threadIdx.x;
    int warp = tid>>5, lane = tid&31;
    if (tid < 16){
        float S = 0.f, Q = 0.f;
#pragma unroll
        for (int i = 0; i < 36; i++){ S += g_p2[i*32+tid*2]; Q += g_p2[i*32+tid*2+1]; }
        float mu = S/NPX, var = Q/NPX - mu*mu;
        float r = rsqrtf(var + EPSB) * g2[tid];
        sc[tid] = r; sh[tid] = bb2[tid] - mu*r;
    }
    for (int i = tid; i < 3200; i += 192) ws[i] = w3[i];
    __syncthreads();
    int r0 = 8*ty - 2;
    for (int i = tid; i < 4608; i += 192){
        int ci = i/288, rr = (i/24)%12, cc = i%24;
        int gy = r0 + rr; float v = 0.f;
        if (gy >= 0 && gy < 24)
            v = fmaxf(g_h2[((size_t)b*16+ci)*576 + gy*24 + cc]*sc[ci] + sh[ci], 0.f);
        in_s[ci][rr][cc] = v;
    }
    __syncthreads();
    int ly = tid/24, lx = tid%24, gy = 8*ty + ly;
    float acc[8];
#pragma unroll
    for (int o = 0; o < 8; o++) acc[o] = 0.f;
    for (int ci = 0; ci < 16; ci++){
#pragma unroll
        for (int ky = 0; ky < 5; ky++){
#pragma unroll
            for (int kx = 0; kx < 5; kx++){
                int gx = lx + kx - 2;
                if (gx >= 0 && gx < 24){
                    float xv = in_s[ci][ly+ky][gx];
#pragma unroll
                    for (int o = 0; o < 8; o++) acc[o] += xv * ws[(o*16+ci)*25 + ky*5 + kx];
                }
            }
        }
    }
#pragma unroll
    for (int o = 0; o < 8; o++) g_h3[((size_t)b*8+o)*576 + gy*24 + lx] = acc[o];
#pragma unroll
    for (int o = 0; o < 8; o++){
        float s = acc[o], q = acc[o]*acc[o];
#pragma unroll
        for (int off = 16; off; off >>= 1){
            s += __shfl_xor_sync(0xffffffffu, s, off);
            q += __shfl_xor_sync(0xffffffffu, q, off);
        }
        if (lane == 0){ sred[warp][o][0] = s; sred[warp][o][1] = q; }
    }
    __syncthreads();
    if (tid < 8){
        float S = 0.f, Q = 0.f;
#pragma unroll
        for (int w = 0; w < 6; w++){ S += sred[w][tid][0]; Q += sred[w][tid][1]; }
        int blk = b*3 + ty;
        g_p3[blk*16 + tid*2+0] = S;
        g_p3[blk*16 + tid*2+1] = Q;
    }
}

__device__ __forceinline__ void ldw(float2 W[4], const float* wr, int c, bool ok){
    if (ok){
        W[0] = *(const float2*)(wr + c);
        W[1] = *(const float2*)(wr + INP + c);
        W[2] = *(const float2*)(wr + 2*INP + c);
        W[3] = *(const float2*)(wr + 3*INP + c);
    } else {
        W[0] = W[1] = W[2] = W[3] = make_float2(0.f, 0.f);
    }
}

// ---------- big weight-streaming GEMM (i,g,o rows; f gate dead since c0=0) ----------
// grid (54, 8) x 128 thr. 256 rows/block (16 passes x 4 warps x 4 rows).
// Activation smem fill computes bn3+relu+assembly on the fly (no k_asm kernel).
__global__ __launch_bounds__(128) void k_gemm(
    const float* __restrict__ w_ih, const float* __restrict__ g3,
    const float* __restrict__ bb3,  const float* __restrict__ vis)
{
    __shared__ __align__(16) ull ls[6*LSTR];
    __shared__ float sc[8], sh[8];
    const int rblk = blockIdx.x, chunk = blockIdx.y, tid = threadIdx.x;
    const int c0 = chunk * CSZ;
    if (tid < 8){
        float S = 0.f, Q = 0.f;
#pragma unroll
        for (int i = 0; i < 36; i++){ S += g_p3[i*16+tid*2]; Q += g_p3[i*16+tid*2+1]; }
        float mu = S/NPX, var = Q/NPX - mu*mu;
        float r = rsqrtf(var + EPSB) * g3[tid];
        sc[tid] = r; sh[tid] = bb3[tid] - mu*r;
    }
    __syncthreads();
    // fill: agent-pair-packed lstm_in slice with zero pad for c >= CSZ
    for (int i = tid; i < 6*CPAD; i += 128){
        int pp = i/CPAD, c = i - pp*CPAD;
        float v0 = 0.f, v1 = 0.f;
        if (c < CSZ){
            int gc = c0 + c;
            int b0 = 2*pp, b1 = b0 + 1;
            if (gc < 4608){
                int ch = gc/576, px = gc - ch*576;
                float r = sc[ch], t = sh[ch];
                v0 = fmaxf(g_h3[(b0*8+ch)*576 + px]*r + t, 0.f);
                v1 = fmaxf(g_h3[(b1*8+ch)*576 + px]*r + t, 0.f);
            } else if (gc < 4624){ int t = gc-4608; v0 = g_op[b0*16+t]; v1 = g_op[b1*16+t]; }
            else if (gc < 4640){   int t = gc-4624; v0 = g_om[b0*16+t]; v1 = g_om[b1*16+t]; }
            else if (gc < 4832){   int r = gc-4640; float o = g_op[r];
                                   v0 = vis[b0*12 + r/16]*o; v1 = vis[b1*12 + r/16]*o; }
            else                {  v0 = g_mm[gc-4832]; v1 = v0; }
        }
        ls[pp*LSTR + c] = pk2(v0, v1);
    }
    __syncthreads();
    const int warp = tid>>5, lane = tid&31;
    const int cb = 2*lane;
    const bool lane_full = (cb + 576 < CSZ);   // ii=9 col-overflow guard (lanes >= 26 pad)

    auto rowptr = [&](int pass)->const float* {
        int ridx = rblk*256 + pass*16 + warp*4;
        int gate = ridx / 4608;
        int gm = (gate==0) ? 0 : ((gate==1) ? 2 : 3);
        return w_ih + (size_t)(gm*4608 + (ridx - gate*4608))*INP + c0;
    };

    const float* wr = rowptr(0);
    float2 Wb[5][4];
    ldw(Wb[0], wr, cb,       true);
    ldw(Wb[1], wr, cb + 64,  true);
    ldw(Wb[2], wr, cb + 128, true);
    ldw(Wb[3], wr, cb + 192, true);

    for (int pass = 0; pass < 16; pass++){
        const float* wrn = (pass < 15) ? rowptr(pass+1) : wr;
        ull acc[4][6];
#pragma unroll
        for (int r = 0; r < 4; r++)
#pragma unroll
            for (int pp = 0; pp < 6; pp++) acc[r][pp] = 0ULL;
#pragma unroll
        for (int ii = 0; ii < 10; ii++){
            // prefetch global slot ii+4 (depth-4; wraps into next pass's ii 0..3)
            {
                const int pii = ii + 4;
                const float* base = (pii < 10) ? wr : wrn;
                const int ii2 = (pii < 10) ? pii : (pii - 10);
                bool ok = (ii2 < 9) || lane_full;
                ldw(Wb[pii % 5], base, cb + 64*ii2, ok);
            }
            // compute slot ii
            float2* W = Wb[ii % 5];
            const int c = cb + 64*ii;
            ull W0x = dup2(W[0].x), W0y = dup2(W[0].y);
            ull W1x = dup2(W[1].x), W1y = dup2(W[1].y);
            ull W2x = dup2(W[2].x), W2y = dup2(W[2].y);
            ull W3x = dup2(W[3].x), W3y = dup2(W[3].y);
#pragma unroll
            for (int pp = 0; pp < 6; pp++){
                ulonglong2 lv = *(const ulonglong2*)&ls[pp*LSTR + c];
                acc[0][pp] = fma2(W0x, lv.x, acc[0][pp]);
                acc[0][pp] = fma2(W0y, lv.y, acc[0][pp]);
                acc[1][pp] = fma2(W1x, lv.x, acc[1][pp]);
                acc[1][pp] = fma2(W1y, lv.y, acc[1][pp]);
                acc[2][pp] = fma2(W2x, lv.x, acc[2][pp]);
                acc[2][pp] = fma2(W2y, lv.y, acc[2][pp]);
                acc[3][pp] = fma2(W3x, lv.x, acc[3][pp]);
                acc[3][pp] = fma2(W3y, lv.y, acc[3][pp]);
            }
        }
        // reduce-scatter: fold rows over xor16 then xor8, butterfly the remaining 6 ulls
        const bool hi16 = (lane & 16) != 0;
#pragma unroll
        for (int pp = 0; pp < 6; pp++){
            ull g0 = hi16 ? acc[0][pp] : acc[2][pp];
            ull g1 = hi16 ? acc[1][pp] : acc[3][pp];
            ull r0 = __shfl_xor_sync(0xffffffffu, g0, 16);
            ull r1 = __shfl_xor_sync(0xffffffffu, g1, 16);
            acc[0][pp] = add2(hi16 ? acc[2][pp] : acc[0][pp], r0);
            acc[1][pp] = add2(hi16 ? acc[3][pp] : acc[1][pp], r1);
        }
        const bool hi8 = (lane & 8) != 0;
#pragma unroll
        for (int pp = 0; pp < 6; pp++){
            ull g = hi8 ? acc[0][pp] : acc[1][pp];
            ull r = __shfl_xor_sync(0xffffffffu, g, 8);
            acc[0][pp] = add2(hi8 ? acc[1][pp] : acc[0][pp], r);
        }
#pragma unroll
        for (int off = 4; off; off >>= 1)
#pragma unroll
            for (int pp = 0; pp < 6; pp++)
                acc[0][pp] = add2(acc[0][pp], __shfl_xor_sync(0xffffffffu, acc[0][pp], off));
        // lane group of 8 holds one full row; lanes 0..5 of each group store agent pairs
        {
            int local = lane & 7;
            int row_off = ((lane >> 3) & 1) + (((lane >> 4) & 1) << 1);
            if (local < 6){
                int rr = rblk*256 + pass*16 + warp*4 + row_off;
                *(ull*)&g_part[((size_t)chunk*13824 + rr)*KA + 2*local] = acc[0][local];
            }
        }
        wr = wrn;
    }
}

// ---------- sum partials + LSTM activations -> relu(h) agent-pair planes ----------
__global__ void k_fin(const float* __restrict__ b_ih, const float* __restrict__ b_hh){
    int idx = blockIdx.x*256 + threadIdx.x;
    if (idx >= KA*HSZ) return;
    int b = idx % KA, h = idx / KA;
    float si = b_ih[h] + b_hh[h];
    float sg = b_ih[9216 + h] + b_hh[9216 + h];
    float so = b_ih[13824 + h] + b_hh[13824 + h];
#pragma unroll
    for (int ch = 0; ch < NCH; ch++){
        const float* pp = g_part + (size_t)ch*13824*KA;
        si += pp[(size_t)h*KA + b];
        sg += pp[(size_t)(4608 + h)*KA + b];
        so += pp[(size_t)(9216 + h)*KA + b];
    }
    float c  = (1.f/(1.f + __expf(-si))) * tanhf(sg);
    float hv = (1.f/(1.f + __expf(-so))) * tanhf(c);
    g_hp[((size_t)(b>>1)*HSZ + h)*2 + (b&1)] = fmaxf(hv, 0.f);
}

// ---------- head GEMM (ah rows 0..127, inf rows 128..319) ----------
__global__ __launch_bounds__(128) void k_hgemm(const float* __restrict__ ah_w,
                                               const float* __restrict__ inf_w){
    __shared__ __align__(16) ull lsu[6*LSTR2];
    int rblk = blockIdx.x, chunk = blockIdx.y, tid = threadIdx.x;
    int c0 = chunk * CSZ2;
    const ull* gsrc = (const ull*)g_hp;
    for (int i = tid; i < 6*CSZ2; i += 128){
        int pp = i/CSZ2, c = i - pp*CSZ2;
        lsu[pp*LSTR2 + c] = gsrc[(size_t)pp*HSZ + c0 + c];
    }
    __syncthreads();
    int warp = tid>>5, lane = tid&31;
    int cb = 2*lane;
    int ridx = rblk*16 + warp*4;
    const float* __restrict__ wb = (ridx < 128) ? ah_w + (size_t)ridx*HSZ + c0
                                                : inf_w + (size_t)(ridx-128)*HSZ + c0;
    ull acc[4][6];
#pragma unroll
    for (int r = 0; r < 4; r++)
#pragma unroll
        for (int pp = 0; pp < 6; pp++) acc[r][pp] = 0ULL;
#pragma unroll
    for (int i = 0; i < 12; i++){
        int c = i*64 + cb;
        float2 wv0 = *(const float2*)(wb + c);
        float2 wv1 = *(const float2*)(wb + HSZ + c);
        float2 wv2 = *(const float2*)(wb + 2*HSZ + c);
        float2 wv3 = *(const float2*)(wb + 3*HSZ + c);
        ull W0x = dup2(wv0.x), W0y = dup2(wv0.y);
        ull W1x = dup2(wv1.x), W1y = dup2(wv1.y);
        ull W2x = dup2(wv2.x), W2y = dup2(wv2.y);
        ull W3x = dup2(wv3.x), W3y = dup2(wv3.y);
#pragma unroll
        for (int pp = 0; pp < 6; pp++){
            ulonglong2 lv = *(const ulonglong2*)&lsu[pp*LSTR2 + c];
            acc[0][pp] = fma2(W0x, lv.x, acc[0][pp]);
            acc[0][pp] = fma2(W0y, lv.y, acc[0][pp]);
            acc[1][pp] = fma2(W1x, lv.x, acc[1][pp]);
            acc[1][pp] = fma2(W1y, lv.y, acc[1][pp]);
            acc[2][pp] = fma2(W2x, lv.x, acc[2][pp]);
            acc[2][pp] = fma2(W2y, lv.y, acc[2][pp]);
            acc[3][pp] = fma2(W3x, lv.x, acc[3][pp]);
            acc[3][pp] = fma2(W3y, lv.y, acc[3][pp]);
        }
    }
#pragma unroll
    for (int r = 0; r < 4; r++)
#pragma unroll
        for (int pp = 0; pp < 6; pp++){
            ull v = acc[r][pp];
#pragma unroll
            for (int off = 16; off; off >>= 1)
                v = add2(v, __shfl_xor_sync(0xffffffffu, v, off));
            acc[r][pp] = v;
        }
    if (lane < 12){
        int pp = lane>>1, hi = lane&1;
#pragma unroll
        for (int r = 0; r < 4; r++){
            float lo_, hi_;
            asm("mov.b64 {%0,%1}, %2;" : "=f"(lo_), "=f"(hi_) : "l"(acc[r][pp]));
            g_part2[((size_t)chunk*HROWS + ridx + r)*KA + lane] = hi ? hi_ : lo_;
        }
    }
}

// ---------- head finalize + action head (single block) ----------
__global__ __launch_bounds__(512) void k_hfinact(const float* __restrict__ ah_b,
                                                 const float* __restrict__ inf_b,
                                                 const float* __restrict__ act_w,
                                                 const float* __restrict__ act_b,
                                                 float* __restrict__ out){
    __shared__ float t[12*128];
    int tid = threadIdx.x;
    for (int idx = tid; idx < HROWS*KA; idx += 512){
        int b = idx % KA, r = idx / KA;
        float s = (r < 128) ? ah_b[r] : inf_b[r-128];
#pragma unroll
        for (int ch = 0; ch < NCH2; ch++)
            s += g_part2[((size_t)ch*HROWS + r)*KA + b];
        if (r < 128) t[b*128 + r] = fmaxf(s, 0.f);
        else         out[192 + b*192 + (r-128)] = s;
    }
    __syncthreads();
    if (tid < 192){
        int b = tid/16, a = tid%16;
        float s = act_b[a];
        for (int q = 0; q < 128; q++) s += t[b*128+q] * act_w[a*128+q];
        out[b*16 + a] = s;
    }
}

extern "C" void kernel_launch(void* const* d_in, const int* in_sizes, int n_in,
                              void* d_out, int out_size){
    const float* x       = (const float*)d_in[0];
    const float* p       = (const float*)d_in[1];
    const float* m       = (const float*)d_in[2];
    const float* vis     = (const float*)d_in[3];
    const float* conv1_w = (const float*)d_in[4];
    const float* bn1_g   = (const float*)d_in[6];
    const float* bn1_b   = (const float*)d_in[7];
    const float* conv2_w = (const float*)d_in[8];
    const float* bn2_g   = (const float*)d_in[10];
    const float* bn2_b   = (const float*)d_in[11];
    const float* conv3_w = (const float*)d_in[12];
    const float* bn3_g   = (const float*)d_in[14];
    const float* bn3_b   = (const float*)d_in[15];
    const float* phys_w  = (const float*)d_in[16];
    const float* phys_b  = (const float*)d_in[17];
    const float* ment_w  = (const float*)d_in[18];
    const float* ment_b  = (const float*)d_in[19];
    const float* w_ih    = (const float*)d_in[20];   // w_hh (21) dead: h0 = 0
    const float* b_ih    = (const float*)d_in[22];
    const float* b_hh    = (const float*)d_in[23];
    const float* ah_w    = (const float*)d_in[24];
    const float* ah_b    = (const float*)d_in[25];
    const float* act_w   = (const float*)d_in[26];
    const float* act_b   = (const float*)d_in[27];
    const float* inf_w   = (const float*)d_in[28];
    const float* inf_b   = (const float*)d_in[29];
    float* out = (float*)d_out;

    k_conv1<<<dim3(12,3), 192>>>(x, conv1_w, p, m, phys_w, phys_b, ment_w, ment_b); // 0
    k_conv2<<<dim3(12,3), 192>>>(conv2_w, bn1_g, bn1_b);                            // 1
    k_conv3<<<dim3(12,3), 192>>>(conv3_w, bn2_g, bn2_b);                            // 2
    k_gemm<<<dim3(NRB, NCH), 128>>>(w_ih, bn3_g, bn3_b, vis);                       // 3 <- ncu
    k_fin<<<216, 256>>>(b_ih, b_hh);                                                // 4
    k_hgemm<<<dim3(20, NCH2), 128>>>(ah_w, inf_w);                                  // 5
    k_hfinact<<<1, 512>>>(ah_b, inf_b, act_w, act_b, out);                          // 6
}